// round 15
// baseline (speedup 1.0000x reference)
#include <cuda_runtime.h>
#include <cuda_fp16.h>
#include <cstdint>
#include <cstddef>

#define DI __device__ __forceinline__

static constexpr int T_LEN    = 128;
static constexpr int D_MODEL_ = 2048;
static constexpr int N_HEADS_ = 16;
static constexpr int D_HEAD_  = 128;
static constexpr int B_SZ     = 64;
static constexpr int M_ROWS   = B_SZ * T_LEN;   // 8192
static constexpr int QKV_LD   = 3 * D_MODEL_;   // 6144

// ---------------- scratch (static device arrays; no allocation) -------------
__device__ __half g_xh  [(size_t)M_ROWS * D_MODEL_];          // x in fp16
__device__ __half g_wqkv[(size_t)3 * D_MODEL_ * D_MODEL_];    // [Wq;Wk;Wv] fp16
__device__ __half g_wo  [(size_t)D_MODEL_ * D_MODEL_];        // Wo fp16
__device__ __half g_qkv [(size_t)M_ROWS * QKV_LD];            // QKV projections
__device__ __half g_attn[(size_t)M_ROWS * D_MODEL_];          // attn output
__device__ float2 g_rope[T_LEN * (D_HEAD_ / 2)];              // cos/sin table

// ---------------- PTX helpers ----------------------------------------------
DI uint32_t smem_u32(const void* p) { return (uint32_t)__cvta_generic_to_shared(p); }

DI void cp_async16(uint32_t dst, const void* src) {
    asm volatile("cp.async.cg.shared.global [%0], [%1], 16;\n" :: "r"(dst), "l"(src) : "memory");
}
DI void cp_commit() { asm volatile("cp.async.commit_group;\n" ::: "memory"); }
template<int N> DI void cp_wait() { asm volatile("cp.async.wait_group %0;\n" :: "n"(N) : "memory"); }

DI void ldsm4(uint32_t* r, const __half* p) {
    uint32_t a = smem_u32(p);
    asm volatile("ldmatrix.sync.aligned.m8n8.x4.shared.b16 {%0,%1,%2,%3}, [%4];\n"
                 : "=r"(r[0]), "=r"(r[1]), "=r"(r[2]), "=r"(r[3]) : "r"(a));
}
DI void ldsm4t(uint32_t* r, const __half* p) {
    uint32_t a = smem_u32(p);
    asm volatile("ldmatrix.sync.aligned.m8n8.x4.trans.shared.b16 {%0,%1,%2,%3}, [%4];\n"
                 : "=r"(r[0]), "=r"(r[1]), "=r"(r[2]), "=r"(r[3]) : "r"(a));
}
DI void mma16816(float* d, const uint32_t* a, uint32_t b0, uint32_t b1) {
    asm volatile("mma.sync.aligned.m16n8k16.row.col.f32.f16.f16.f32 "
                 "{%0,%1,%2,%3}, {%4,%5,%6,%7}, {%8,%9}, {%0,%1,%2,%3};\n"
                 : "+f"(d[0]), "+f"(d[1]), "+f"(d[2]), "+f"(d[3])
                 : "r"(a[0]), "r"(a[1]), "r"(a[2]), "r"(a[3]), "r"(b0), "r"(b1));
}

DI void store2(__half* p, float a, float b) {
    *reinterpret_cast<__half2*>(p) = __floats2half2_rn(a, b);
}
DI void store2(float* p, float a, float b) {
    *reinterpret_cast<float2*>(p) = make_float2(a, b);
}

// ---------------- fp32 -> fp16 convert (x) ----------------------------------
__global__ void cvt_kernel(const float* __restrict__ in, __half* __restrict__ out, int n4) {
    int i = blockIdx.x * blockDim.x + threadIdx.x;
    if (i < n4) {
        float4 v = reinterpret_cast<const float4*>(in)[i];
        reinterpret_cast<__half2*>(out)[2 * i]     = __floats2half2_rn(v.x, v.y);
        reinterpret_cast<__half2*>(out)[2 * i + 1] = __floats2half2_rn(v.z, v.w);
    }
}

// ---------------- weight converts, one launch (4 segments) ------------------
__global__ void cvtw_kernel(const float* __restrict__ wq, const float* __restrict__ wk,
                            const float* __restrict__ wv, const float* __restrict__ wo,
                            __half* __restrict__ wqkv, __half* __restrict__ woh) {
    const int seg = blockIdx.y;
    const float* src = (seg == 0) ? wq : (seg == 1) ? wk : (seg == 2) ? wv : wo;
    __half* dst = (seg < 3) ? (wqkv + (size_t)seg * D_MODEL_ * D_MODEL_) : woh;
    int i = blockIdx.x * blockDim.x + threadIdx.x;   // n4 = 2048*2048/4
    float4 v = reinterpret_cast<const float4*>(src)[i];
    reinterpret_cast<__half2*>(dst)[2 * i]     = __floats2half2_rn(v.x, v.y);
    reinterpret_cast<__half2*>(dst)[2 * i + 1] = __floats2half2_rn(v.z, v.w);
}

// ---------------- RoPE cos/sin table ----------------------------------------
__global__ void rope_tab_kernel() {
    int i = blockIdx.x * blockDim.x + threadIdx.x;   // 0 .. 8191
    int t = i >> 6, k = i & 63;                      // d = 2k
    float theta = exp2f(-(float)(2 * k) * (13.287712379549449f / 128.0f));
    float fr = (float)t * theta;
    float sn, cs;
    sincosf(fr, &sn, &cs);
    g_rope[i] = make_float2(cs, sn);
}

// ---------------- NT GEMM: C[M,N] = A[M,K] * B[N,K]^T, fp16 in, fp32 acc ----
// Block 256x128, BK=64, 3-stage cp.async pipeline, ONE __syncthreads per
// k-iteration. 8 warps (4m x 2n), warp tile 64x64 -> 8 ldsm : 32 mma per k16.
// ROPE: apply rotary embedding to cols < 4096 (Q,K regions) in the epilogue.
static constexpr int G_BM = 256, G_BN = 128, G_BK = 64, G_ST = 3;
static constexpr int G_LDS   = G_BK + 8;                      // 72 halves = 144B rows
static constexpr int G_TILEA = G_BM * G_LDS;                  // A halves per stage
static constexpr int G_TILEB = G_BN * G_LDS;                  // B halves per stage
static constexpr int G_SMEM  = G_ST * (G_TILEA + G_TILEB) * (int)sizeof(__half); // 165888

template<typename OutT, bool ROPE>
__global__ __launch_bounds__(256, 1)
void gemm_nt(const __half* __restrict__ A, int lda,
             const __half* __restrict__ B, int ldb,
             OutT* __restrict__ C, int ldc, int K)
{
    extern __shared__ __half sm[];
    __half* As0 = sm;                       // [G_ST][G_TILEA]
    __half* Bs0 = sm + G_ST * G_TILEA;      // [G_ST][G_TILEB]

    const int tid = threadIdx.x, lane = tid & 31, warp = tid >> 5;
    const int wm = (warp >> 1) * 64, wn = (warp & 1) * 64;
    const size_t bm = (size_t)blockIdx.y * G_BM, bn = (size_t)blockIdx.x * G_BN;
    const __half* Ag = A + bm * lda;
    const __half* Bg = B + bn * ldb;

    float acc[4][8][4];
#pragma unroll
    for (int i = 0; i < 4; i++)
#pragma unroll
        for (int j = 0; j < 8; j++)
#pragma unroll
            for (int l = 0; l < 4; l++) acc[i][j][l] = 0.f;

    const int lr = tid >> 3, lch = (tid & 7) * 8;   // 32 rows/pass, 8x16B chunks/row

    auto load_tile = [&](int s, int k0) {
        __half* as = As0 + s * G_TILEA;
        __half* bs = Bs0 + s * G_TILEB;
#pragma unroll
        for (int i = 0; i < 8; i++) {
            int r = lr + i * 32;
            cp_async16(smem_u32(as + r * G_LDS + lch), Ag + (size_t)r * lda + k0 + lch);
        }
#pragma unroll
        for (int i = 0; i < 4; i++) {
            int r = lr + i * 32;
            cp_async16(smem_u32(bs + r * G_LDS + lch), Bg + (size_t)r * ldb + k0 + lch);
        }
        cp_commit();
    };

    // prologue: stages 0,1 in flight
    load_tile(0, 0);
    load_tile(1, G_BK);

    const int KT = K / G_BK;   // 32
    for (int kt = 0; kt < KT; ++kt) {
        if (kt == KT - 1) cp_wait<0>(); else cp_wait<1>();   // stage kt complete
        __syncthreads();                                     // stage (kt-1)%3 now free
        if (kt + 2 < KT) load_tile((kt + 2) % 3, (kt + 2) * G_BK);

        const __half* as = As0 + (kt % 3) * G_TILEA;
        const __half* bs = Bs0 + (kt % 3) * G_TILEB;
#pragma unroll
        for (int kk = 0; kk < G_BK; kk += 16) {
            uint32_t ra[4][4], rb[4][4];
#pragma unroll
            for (int mt = 0; mt < 4; mt++)
                ldsm4(ra[mt], as + (wm + mt * 16 + (lane & 15)) * G_LDS + kk + (lane >> 4) * 8);
#pragma unroll
            for (int nt2 = 0; nt2 < 4; nt2++)
                ldsm4(rb[nt2], bs + (wn + nt2 * 16 + ((lane >> 4) << 3) + (lane & 7)) * G_LDS
                                  + kk + ((lane >> 3) & 1) * 8);
#pragma unroll
            for (int mt = 0; mt < 4; mt++)
#pragma unroll
                for (int nt = 0; nt < 8; nt++)
                    mma16816(acc[mt][nt], ra[mt], rb[nt >> 1][(nt & 1) * 2], rb[nt >> 1][(nt & 1) * 2 + 1]);
        }
    }

#pragma unroll
    for (int mt = 0; mt < 4; mt++)
#pragma unroll
        for (int nt = 0; nt < 8; nt++) {
            size_t r = bm + wm + mt * 16 + (lane >> 2);
            size_t c = bn + wn + nt * 8 + (lane & 3) * 2;
            float a0 = acc[mt][nt][0], a1 = acc[mt][nt][1];
            float a2 = acc[mt][nt][2], a3 = acc[mt][nt][3];
            if (ROPE && c < 4096) {
                int d2 = ((int)c & (D_HEAD_ - 1)) >> 1;   // head-dim pair index
                int t0 = (int)(r & (T_LEN - 1));          // rows r, r+8 in same t-block
                float2 cs0 = g_rope[t0 * 64 + d2];
                float2 cs1 = g_rope[(t0 + 8) * 64 + d2];
                float e0 = a0, o0 = a1;
                a0 = e0 * cs0.x - o0 * cs0.y;
                a1 = e0 * cs0.y + o0 * cs0.x;
                float e1 = a2, o1 = a3;
                a2 = e1 * cs1.x - o1 * cs1.y;
                a3 = e1 * cs1.y + o1 * cs1.x;
            }
            store2(C + r * ldc + c,       a0, a1);
            store2(C + (r + 8) * ldc + c, a2, a3);
        }
}

// ---------------- fused attention v2: one CTA per (b, h) --------------------
// Warp w owns query rows [16w, 16w+16). Softmax fully in registers.
// SMEM: Q (later P) + K + V, each [128][136] halves. cp.async prefetch of V
// overlaps the QK^T phase. Occupancy 2.
static constexpr int A_LD = 136;
static constexpr int ATTN_SMEM = 3 * 128 * A_LD * (int)sizeof(__half);  // 104448

__global__ __launch_bounds__(256, 2)
void attn_kernel(const __half* __restrict__ qkv, __half* __restrict__ attn)
{
    extern __shared__ char sm_raw[];
    __half* Qs = reinterpret_cast<__half*>(sm_raw);   // Q, later P
    __half* Ks = Qs + 128 * A_LD;
    __half* Vs = Ks + 128 * A_LD;

    const int h = blockIdx.x, b = blockIdx.y;
    const int tid = threadIdx.x, lane = tid & 31, warp = tid >> 5;
    const size_t rowBase = (size_t)b * 128;
    const __half* Qg = qkv + rowBase * QKV_LD + (size_t)h * 128;
    const __half* Kg = Qg + D_MODEL_;
    const __half* Vg = Qg + 2 * D_MODEL_;

    // async loads: group0 = Q+K, group1 = V
#pragma unroll
    for (int i = 0; i < 8; i++) {
        int c = tid + i * 256;
        int r = c >> 4, ch = (c & 15) * 8;
        cp_async16(smem_u32(Qs + r * A_LD + ch), Qg + (size_t)r * QKV_LD + ch);
        cp_async16(smem_u32(Ks + r * A_LD + ch), Kg + (size_t)r * QKV_LD + ch);
    }
    cp_commit();
#pragma unroll
    for (int i = 0; i < 8; i++) {
        int c = tid + i * 256;
        int r = c >> 4, ch = (c & 15) * 8;
        cp_async16(smem_u32(Vs + r * A_LD + ch), Vg + (size_t)r * QKV_LD + ch);
    }
    cp_commit();

    cp_wait<1>();          // Q, K ready (V still in flight)
    __syncthreads();

    // ---- phase 1: S = Q K^T for this warp's 16 rows ----
    float acc[16][4];
#pragma unroll
    for (int j = 0; j < 16; j++)
#pragma unroll
        for (int l = 0; l < 4; l++) acc[j][l] = 0.f;

#pragma unroll
    for (int kk = 0; kk < 128; kk += 16) {
        uint32_t ra[4], rb[8][4];
        ldsm4(ra, Qs + (16 * warp + (lane & 15)) * A_LD + kk + (lane >> 4) * 8);
#pragma unroll
        for (int nt2 = 0; nt2 < 8; nt2++)
            ldsm4(rb[nt2], Ks + (nt2 * 16 + ((lane >> 4) << 3) + (lane & 7)) * A_LD
                              + kk + ((lane >> 3) & 1) * 8);
#pragma unroll
        for (int nt = 0; nt < 16; nt++)
            mma16816(acc[nt], ra, rb[nt >> 1][(nt & 1) * 2], rb[nt >> 1][(nt & 1) * 2 + 1]);
    }

    // ---- softmax in registers (rows r0 = 16w + lane>>2 and r0+8) ----
    const int r0 = 16 * warp + (lane >> 2);
    const int r1 = r0 + 8;
    const float scale = 0.08838834764831845f;  // 1/sqrt(128)
    float m0 = -1e30f, m1 = -1e30f;
#pragma unroll
    for (int nt = 0; nt < 16; nt++) {
        int c0 = nt * 8 + (lane & 3) * 2;
#pragma unroll
        for (int jj = 0; jj < 2; jj++) {
            int c = c0 + jj;
            float v0 = (c <= r0) ? acc[nt][jj] * scale : -1e30f;
            float v1 = (c <= r1) ? acc[nt][jj + 2] * scale : -1e30f;
            acc[nt][jj] = v0;  acc[nt][jj + 2] = v1;
            m0 = fmaxf(m0, v0); m1 = fmaxf(m1, v1);
        }
    }
#pragma unroll
    for (int o = 1; o <= 2; o <<= 1) {
        m0 = fmaxf(m0, __shfl_xor_sync(0xffffffffu, m0, o));
        m1 = fmaxf(m1, __shfl_xor_sync(0xffffffffu, m1, o));
    }
    float s0 = 0.f, s1 = 0.f;
#pragma unroll
    for (int nt = 0; nt < 16; nt++) {
#pragma unroll
        for (int jj = 0; jj < 2; jj++) {
            float e0 = __expf(acc[nt][jj] - m0);
            float e1 = __expf(acc[nt][jj + 2] - m1);
            acc[nt][jj] = e0;  acc[nt][jj + 2] = e1;
            s0 += e0;  s1 += e1;
        }
    }
#pragma unroll
    for (int o = 1; o <= 2; o <<= 1) {
        s0 += __shfl_xor_sync(0xffffffffu, s0, o);
        s1 += __shfl_xor_sync(0xffffffffu, s1, o);
    }
    const float inv0 = 1.f / s0, inv1 = 1.f / s1;

    cp_wait<0>();          // V ready
    __syncthreads();       // all threads' V chunks visible

    // ---- P (fp16) into Q buffer, own rows only ----
    __half* Ps = Qs;
#pragma unroll
    for (int nt = 0; nt < 16; nt++) {
        int c = nt * 8 + (lane & 3) * 2;
        store2(Ps + r0 * A_LD + c, acc[nt][0] * inv0, acc[nt][1] * inv0);
        store2(Ps + r1 * A_LD + c, acc[nt][2] * inv1, acc[nt][3] * inv1);
    }
    __syncwarp();

    // ---- phase 2: O = P V ----
    float o[16][4];
#pragma unroll
    for (int j = 0; j < 16; j++)
#pragma unroll
        for (int l = 0; l < 4; l++) o[j][l] = 0.f;

#pragma unroll
    for (int kk = 0; kk < 128; kk += 16) {
        uint32_t ra[4], rb[8][4];
        ldsm4(ra, Ps + (16 * warp + (lane & 15)) * A_LD + kk + (lane >> 4) * 8);
#pragma unroll
        for (int nt2 = 0; nt2 < 8; nt2++)
            ldsm4t(rb[nt2], Vs + (kk + (lane & 15)) * A_LD + nt2 * 16 + ((lane >> 4) << 3));
#pragma unroll
        for (int nt = 0; nt < 16; nt++)
            mma16816(o[nt], ra, rb[nt >> 1][(nt & 1) * 2], rb[nt >> 1][(nt & 1) * 2 + 1]);
    }

#pragma unroll
    for (int nt = 0; nt < 16; nt++) {
        size_t gr = rowBase + r0;
        size_t c = (size_t)h * 128 + nt * 8 + (lane & 3) * 2;
        store2(attn + gr * D_MODEL_ + c,       o[nt][0], o[nt][1]);
        store2(attn + (gr + 8) * D_MODEL_ + c, o[nt][2], o[nt][3]);
    }
}

// ---------------- launch -----------------------------------------------------
extern "C" void kernel_launch(void* const* d_in, const int* in_sizes, int n_in,
                              void* d_out, int out_size)
{
    (void)in_sizes; (void)n_in; (void)out_size;
    const float* x  = (const float*)d_in[0];
    const float* wq = (const float*)d_in[1];
    const float* wk = (const float*)d_in[2];
    const float* wv = (const float*)d_in[3];
    const float* wo = (const float*)d_in[4];
    // d_in[5] = mask: causal, known statically — ignored.
    float* out = (float*)d_out;

    __half *xh, *wqkv, *woh, *qkv, *attn;
    cudaGetSymbolAddress((void**)&xh,   g_xh);
    cudaGetSymbolAddress((void**)&wqkv, g_wqkv);
    cudaGetSymbolAddress((void**)&woh,  g_wo);
    cudaGetSymbolAddress((void**)&qkv,  g_qkv);
    cudaGetSymbolAddress((void**)&attn, g_attn);

    // fp32 -> fp16 conversions + rope table
    {
        int n = M_ROWS * D_MODEL_;
        cvt_kernel<<<n / 1024, 256>>>(x, xh, n / 4);
        int m4 = D_MODEL_ * D_MODEL_ / 4;
        cvtw_kernel<<<dim3(m4 / 256, 4), 256>>>(wq, wk, wv, wo, wqkv, woh);
        rope_tab_kernel<<<32, 256>>>();
    }

    // QKV = x @ [Wq;Wk;Wv]^T with fused RoPE on Q,K   (M=8192, N=6144, K=2048)
    cudaFuncSetAttribute(gemm_nt<__half, true>,
                         cudaFuncAttributeMaxDynamicSharedMemorySize, G_SMEM);
    gemm_nt<__half, true><<<dim3(QKV_LD / G_BN, M_ROWS / G_BM), 256, G_SMEM>>>(
        xh, D_MODEL_, wqkv, D_MODEL_, qkv, QKV_LD, D_MODEL_);

    // fused attention, one CTA per (head, batch)
    cudaFuncSetAttribute(attn_kernel, cudaFuncAttributeMaxDynamicSharedMemorySize, ATTN_SMEM);
    attn_kernel<<<dim3(N_HEADS_, B_SZ), 256, ATTN_SMEM>>>(qkv, attn);

    // out = attn @ Wo^T   (M=8192, N=2048, K=2048), fp32 output
    cudaFuncSetAttribute(gemm_nt<float, false>,
                         cudaFuncAttributeMaxDynamicSharedMemorySize, G_SMEM);
    gemm_nt<float, false><<<dim3(D_MODEL_ / G_BN, M_ROWS / G_BM), 256, G_SMEM>>>(
        attn, D_MODEL_, woh, D_MODEL_, out, D_MODEL_, D_MODEL_);
}

// round 16
// speedup vs baseline: 1.1650x; 1.1650x over previous
#include <cuda_runtime.h>
#include <cuda_fp16.h>
#include <cstdint>
#include <cstddef>

#define DI __device__ __forceinline__

static constexpr int T_LEN    = 128;
static constexpr int D_MODEL_ = 2048;
static constexpr int N_HEADS_ = 16;
static constexpr int D_HEAD_  = 128;
static constexpr int B_SZ     = 64;
static constexpr int M_ROWS   = B_SZ * T_LEN;   // 8192
static constexpr int QKV_LD   = 3 * D_MODEL_;   // 6144

// ---------------- scratch (static device arrays; no allocation) -------------
__device__ __half g_xh  [(size_t)M_ROWS * D_MODEL_];          // x in fp16
__device__ __half g_wqkv[(size_t)3 * D_MODEL_ * D_MODEL_];    // [Wq;Wk;Wv] fp16
__device__ __half g_wo  [(size_t)D_MODEL_ * D_MODEL_];        // Wo fp16
__device__ __half g_qkv [(size_t)M_ROWS * QKV_LD];            // QKV projections
__device__ __half g_attn[(size_t)M_ROWS * D_MODEL_];          // attn output
__device__ float2 g_rope[T_LEN * (D_HEAD_ / 2)];              // cos/sin table

// ---------------- PTX helpers ----------------------------------------------
DI uint32_t smem_u32(const void* p) { return (uint32_t)__cvta_generic_to_shared(p); }

DI void cp_async16(uint32_t dst, const void* src) {
    asm volatile("cp.async.cg.shared.global [%0], [%1], 16;\n" :: "r"(dst), "l"(src) : "memory");
}
DI void cp_commit() { asm volatile("cp.async.commit_group;\n" ::: "memory"); }
template<int N> DI void cp_wait() { asm volatile("cp.async.wait_group %0;\n" :: "n"(N) : "memory"); }

DI void ldsm4(uint32_t* r, const __half* p) {
    uint32_t a = smem_u32(p);
    asm volatile("ldmatrix.sync.aligned.m8n8.x4.shared.b16 {%0,%1,%2,%3}, [%4];\n"
                 : "=r"(r[0]), "=r"(r[1]), "=r"(r[2]), "=r"(r[3]) : "r"(a));
}
DI void ldsm4t(uint32_t* r, const __half* p) {
    uint32_t a = smem_u32(p);
    asm volatile("ldmatrix.sync.aligned.m8n8.x4.trans.shared.b16 {%0,%1,%2,%3}, [%4];\n"
                 : "=r"(r[0]), "=r"(r[1]), "=r"(r[2]), "=r"(r[3]) : "r"(a));
}
DI void mma16816(float* d, const uint32_t* a, uint32_t b0, uint32_t b1) {
    asm volatile("mma.sync.aligned.m16n8k16.row.col.f32.f16.f16.f32 "
                 "{%0,%1,%2,%3}, {%4,%5,%6,%7}, {%8,%9}, {%0,%1,%2,%3};\n"
                 : "+f"(d[0]), "+f"(d[1]), "+f"(d[2]), "+f"(d[3])
                 : "r"(a[0]), "r"(a[1]), "r"(a[2]), "r"(a[3]), "r"(b0), "r"(b1));
}

DI void store2(__half* p, float a, float b) {
    *reinterpret_cast<__half2*>(p) = __floats2half2_rn(a, b);
}
DI void store2(float* p, float a, float b) {
    *reinterpret_cast<float2*>(p) = make_float2(a, b);
}

// ---------------- fp32 -> fp16 convert (x) ----------------------------------
__global__ void cvt_kernel(const float* __restrict__ in, __half* __restrict__ out, int n4) {
    int i = blockIdx.x * blockDim.x + threadIdx.x;
    if (i < n4) {
        float4 v = reinterpret_cast<const float4*>(in)[i];
        reinterpret_cast<__half2*>(out)[2 * i]     = __floats2half2_rn(v.x, v.y);
        reinterpret_cast<__half2*>(out)[2 * i + 1] = __floats2half2_rn(v.z, v.w);
    }
}

// ---------------- weight converts, one launch (4 segments) ------------------
__global__ void cvtw_kernel(const float* __restrict__ wq, const float* __restrict__ wk,
                            const float* __restrict__ wv, const float* __restrict__ wo,
                            __half* __restrict__ wqkv, __half* __restrict__ woh) {
    const int seg = blockIdx.y;
    const float* src = (seg == 0) ? wq : (seg == 1) ? wk : (seg == 2) ? wv : wo;
    __half* dst = (seg < 3) ? (wqkv + (size_t)seg * D_MODEL_ * D_MODEL_) : woh;
    int i = blockIdx.x * blockDim.x + threadIdx.x;   // n4 = 2048*2048/4
    float4 v = reinterpret_cast<const float4*>(src)[i];
    reinterpret_cast<__half2*>(dst)[2 * i]     = __floats2half2_rn(v.x, v.y);
    reinterpret_cast<__half2*>(dst)[2 * i + 1] = __floats2half2_rn(v.z, v.w);
}

// ---------------- RoPE cos/sin table ----------------------------------------
__global__ void rope_tab_kernel() {
    int i = blockIdx.x * blockDim.x + threadIdx.x;   // 0 .. 8191
    int t = i >> 6, k = i & 63;                      // d = 2k
    float theta = exp2f(-(float)(2 * k) * (13.287712379549449f / 128.0f));
    float fr = (float)t * theta;
    float sn, cs;
    sincosf(fr, &sn, &cs);
    g_rope[i] = make_float2(cs, sn);
}

// ---------------- NT GEMM: C[M,N] = A[M,K] * B[N,K]^T, fp16 in, fp32 acc ----
// Block 128x128, BK=64, 3-stage cp.async pipeline, ONE __syncthreads per
// k-iteration. 8 warps (4m x 2n), warp tile 32x64 (R14 operating point:
// 128 regs -> occupancy 2 -> 4 warps/SMSP).
// R16 change: prefetch load_tile is issued AFTER the first k16's ldsm batch,
// so the 12 cp.async/thread drain in the LSU while HMMA executes instead of
// serializing at the head of each stage.
// ROPE: apply rotary embedding to cols < 4096 (Q,K regions) in the epilogue.
static constexpr int G_BM = 128, G_BN = 128, G_BK = 64, G_ST = 3;
static constexpr int G_LDS  = G_BK + 8;                       // 72 halves = 144B rows
static constexpr int G_TILE = G_BM * G_LDS;                   // halves per matrix/stage
static constexpr int G_SMEM = G_ST * 2 * G_TILE * (int)sizeof(__half);  // 110592 B

template<typename OutT, bool ROPE>
__global__ __launch_bounds__(256, 2)
void gemm_nt(const __half* __restrict__ A, int lda,
             const __half* __restrict__ B, int ldb,
             OutT* __restrict__ C, int ldc, int K)
{
    extern __shared__ __half sm[];
    __half* As0 = sm;                    // [G_ST][G_TILE]
    __half* Bs0 = sm + G_ST * G_TILE;

    const int tid = threadIdx.x, lane = tid & 31, warp = tid >> 5;
    const int wm = (warp >> 1) * 32, wn = (warp & 1) * 64;
    const size_t bm = (size_t)blockIdx.y * G_BM, bn = (size_t)blockIdx.x * G_BN;
    const __half* Ag = A + bm * lda;
    const __half* Bg = B + bn * ldb;

    float acc[2][8][4];
#pragma unroll
    for (int i = 0; i < 2; i++)
#pragma unroll
        for (int j = 0; j < 8; j++)
#pragma unroll
            for (int l = 0; l < 4; l++) acc[i][j][l] = 0.f;

    const int lr = tid >> 3, lch = (tid & 7) * 8;   // 32 rows/pass, 8 chunks/row

    auto load_tile = [&](int s, int k0) {
        __half* as = As0 + s * G_TILE;
        __half* bs = Bs0 + s * G_TILE;
#pragma unroll
        for (int i = 0; i < 4; i++) {
            int r = lr + i * 32;
            cp_async16(smem_u32(as + r * G_LDS + lch), Ag + (size_t)r * lda + k0 + lch);
            cp_async16(smem_u32(bs + r * G_LDS + lch), Bg + (size_t)r * ldb + k0 + lch);
        }
        cp_commit();
    };

    // A/B fragment loaders for one k16 slice
    auto load_frags = [&](const __half* as, const __half* bs, int kk,
                          uint32_t (&ra)[2][4], uint32_t (&rb)[4][4]) {
#pragma unroll
        for (int mt = 0; mt < 2; mt++)
            ldsm4(ra[mt], as + (wm + mt * 16 + (lane & 15)) * G_LDS + kk + (lane >> 4) * 8);
#pragma unroll
        for (int nt2 = 0; nt2 < 4; nt2++)
            ldsm4(rb[nt2], bs + (wn + nt2 * 16 + ((lane >> 4) << 3) + (lane & 7)) * G_LDS
                              + kk + ((lane >> 3) & 1) * 8);
    };
    auto do_mma = [&](uint32_t (&ra)[2][4], uint32_t (&rb)[4][4]) {
#pragma unroll
        for (int mt = 0; mt < 2; mt++)
#pragma unroll
            for (int nt = 0; nt < 8; nt++)
                mma16816(acc[mt][nt], ra[mt], rb[nt >> 1][(nt & 1) * 2], rb[nt >> 1][(nt & 1) * 2 + 1]);
    };

    // prologue: stages 0,1 in flight
    load_tile(0, 0);
    load_tile(1, G_BK);

    const int KT = K / G_BK;   // 32
    for (int kt = 0; kt < KT; ++kt) {
        if (kt == KT - 1) cp_wait<0>(); else cp_wait<1>();   // stage kt complete
        __syncthreads();                                     // stage (kt-1)%3 now free

        const __half* as = As0 + (kt % 3) * G_TILE;
        const __half* bs = Bs0 + (kt % 3) * G_TILE;

        // first k16: ldsm BEFORE the prefetch, so compute starts immediately;
        // the cp.async stream then drains under the mma stream.
        {
            uint32_t ra[2][4], rb[4][4];
            load_frags(as, bs, 0, ra, rb);
            if (kt + 2 < KT) load_tile((kt + 2) % 3, (kt + 2) * G_BK);
            do_mma(ra, rb);
        }
#pragma unroll
        for (int kk = 16; kk < G_BK; kk += 16) {
            uint32_t ra[2][4], rb[4][4];
            load_frags(as, bs, kk, ra, rb);
            do_mma(ra, rb);
        }
    }

#pragma unroll
    for (int mt = 0; mt < 2; mt++)
#pragma unroll
        for (int nt = 0; nt < 8; nt++) {
            size_t r = bm + wm + mt * 16 + (lane >> 2);
            size_t c = bn + wn + nt * 8 + (lane & 3) * 2;
            float a0 = acc[mt][nt][0], a1 = acc[mt][nt][1];
            float a2 = acc[mt][nt][2], a3 = acc[mt][nt][3];
            if (ROPE && c < 4096) {
                int d2 = ((int)c & (D_HEAD_ - 1)) >> 1;   // head-dim pair index
                int t0 = (int)(r & (T_LEN - 1));          // rows r, r+8 in same t-block
                float2 cs0 = g_rope[t0 * 64 + d2];
                float2 cs1 = g_rope[(t0 + 8) * 64 + d2];
                float e0 = a0, o0 = a1;
                a0 = e0 * cs0.x - o0 * cs0.y;
                a1 = e0 * cs0.y + o0 * cs0.x;
                float e1 = a2, o1 = a3;
                a2 = e1 * cs1.x - o1 * cs1.y;
                a3 = e1 * cs1.y + o1 * cs1.x;
            }
            store2(C + r * ldc + c,       a0, a1);
            store2(C + (r + 8) * ldc + c, a2, a3);
        }
}

// ---------------- fused attention v2: one CTA per (b, h) --------------------
// Warp w owns query rows [16w, 16w+16). Softmax fully in registers.
// SMEM: Q (later P) + K + V, each [128][136] halves. cp.async prefetch of V
// overlaps the QK^T phase. Occupancy 2.
static constexpr int A_LD = 136;
static constexpr int ATTN_SMEM = 3 * 128 * A_LD * (int)sizeof(__half);  // 104448

__global__ __launch_bounds__(256, 2)
void attn_kernel(const __half* __restrict__ qkv, __half* __restrict__ attn)
{
    extern __shared__ char sm_raw[];
    __half* Qs = reinterpret_cast<__half*>(sm_raw);   // Q, later P
    __half* Ks = Qs + 128 * A_LD;
    __half* Vs = Ks + 128 * A_LD;

    const int h = blockIdx.x, b = blockIdx.y;
    const int tid = threadIdx.x, lane = tid & 31, warp = tid >> 5;
    const size_t rowBase = (size_t)b * 128;
    const __half* Qg = qkv + rowBase * QKV_LD + (size_t)h * 128;
    const __half* Kg = Qg + D_MODEL_;
    const __half* Vg = Qg + 2 * D_MODEL_;

    // async loads: group0 = Q+K, group1 = V
#pragma unroll
    for (int i = 0; i < 8; i++) {
        int c = tid + i * 256;
        int r = c >> 4, ch = (c & 15) * 8;
        cp_async16(smem_u32(Qs + r * A_LD + ch), Qg + (size_t)r * QKV_LD + ch);
        cp_async16(smem_u32(Ks + r * A_LD + ch), Kg + (size_t)r * QKV_LD + ch);
    }
    cp_commit();
#pragma unroll
    for (int i = 0; i < 8; i++) {
        int c = tid + i * 256;
        int r = c >> 4, ch = (c & 15) * 8;
        cp_async16(smem_u32(Vs + r * A_LD + ch), Vg + (size_t)r * QKV_LD + ch);
    }
    cp_commit();

    cp_wait<1>();          // Q, K ready (V still in flight)
    __syncthreads();

    // ---- phase 1: S = Q K^T for this warp's 16 rows ----
    float acc[16][4];
#pragma unroll
    for (int j = 0; j < 16; j++)
#pragma unroll
        for (int l = 0; l < 4; l++) acc[j][l] = 0.f;

#pragma unroll
    for (int kk = 0; kk < 128; kk += 16) {
        uint32_t ra[4], rb[8][4];
        ldsm4(ra, Qs + (16 * warp + (lane & 15)) * A_LD + kk + (lane >> 4) * 8);
#pragma unroll
        for (int nt2 = 0; nt2 < 8; nt2++)
            ldsm4(rb[nt2], Ks + (nt2 * 16 + ((lane >> 4) << 3) + (lane & 7)) * A_LD
                              + kk + ((lane >> 3) & 1) * 8);
#pragma unroll
        for (int nt = 0; nt < 16; nt++)
            mma16816(acc[nt], ra, rb[nt >> 1][(nt & 1) * 2], rb[nt >> 1][(nt & 1) * 2 + 1]);
    }

    // ---- softmax in registers (rows r0 = 16w + lane>>2 and r0+8) ----
    const int r0 = 16 * warp + (lane >> 2);
    const int r1 = r0 + 8;
    const float scale = 0.08838834764831845f;  // 1/sqrt(128)
    float m0 = -1e30f, m1 = -1e30f;
#pragma unroll
    for (int nt = 0; nt < 16; nt++) {
        int c0 = nt * 8 + (lane & 3) * 2;
#pragma unroll
        for (int jj = 0; jj < 2; jj++) {
            int c = c0 + jj;
            float v0 = (c <= r0) ? acc[nt][jj] * scale : -1e30f;
            float v1 = (c <= r1) ? acc[nt][jj + 2] * scale : -1e30f;
            acc[nt][jj] = v0;  acc[nt][jj + 2] = v1;
            m0 = fmaxf(m0, v0); m1 = fmaxf(m1, v1);
        }
    }
#pragma unroll
    for (int o = 1; o <= 2; o <<= 1) {
        m0 = fmaxf(m0, __shfl_xor_sync(0xffffffffu, m0, o));
        m1 = fmaxf(m1, __shfl_xor_sync(0xffffffffu, m1, o));
    }
    float s0 = 0.f, s1 = 0.f;
#pragma unroll
    for (int nt = 0; nt < 16; nt++) {
#pragma unroll
        for (int jj = 0; jj < 2; jj++) {
            float e0 = __expf(acc[nt][jj] - m0);
            float e1 = __expf(acc[nt][jj + 2] - m1);
            acc[nt][jj] = e0;  acc[nt][jj + 2] = e1;
            s0 += e0;  s1 += e1;
        }
    }
#pragma unroll
    for (int o = 1; o <= 2; o <<= 1) {
        s0 += __shfl_xor_sync(0xffffffffu, s0, o);
        s1 += __shfl_xor_sync(0xffffffffu, s1, o);
    }
    const float inv0 = 1.f / s0, inv1 = 1.f / s1;

    cp_wait<0>();          // V ready
    __syncthreads();       // all threads' V chunks visible

    // ---- P (fp16) into Q buffer, own rows only ----
    __half* Ps = Qs;
#pragma unroll
    for (int nt = 0; nt < 16; nt++) {
        int c = nt * 8 + (lane & 3) * 2;
        store2(Ps + r0 * A_LD + c, acc[nt][0] * inv0, acc[nt][1] * inv0);
        store2(Ps + r1 * A_LD + c, acc[nt][2] * inv1, acc[nt][3] * inv1);
    }
    __syncwarp();

    // ---- phase 2: O = P V ----
    float o[16][4];
#pragma unroll
    for (int j = 0; j < 16; j++)
#pragma unroll
        for (int l = 0; l < 4; l++) o[j][l] = 0.f;

#pragma unroll
    for (int kk = 0; kk < 128; kk += 16) {
        uint32_t ra[4], rb[8][4];
        ldsm4(ra, Ps + (16 * warp + (lane & 15)) * A_LD + kk + (lane >> 4) * 8);
#pragma unroll
        for (int nt2 = 0; nt2 < 8; nt2++)
            ldsm4t(rb[nt2], Vs + (kk + (lane & 15)) * A_LD + nt2 * 16 + ((lane >> 4) << 3));
#pragma unroll
        for (int nt = 0; nt < 16; nt++)
            mma16816(o[nt], ra, rb[nt >> 1][(nt & 1) * 2], rb[nt >> 1][(nt & 1) * 2 + 1]);
    }

#pragma unroll
    for (int nt = 0; nt < 16; nt++) {
        size_t gr = rowBase + r0;
        size_t c = (size_t)h * 128 + nt * 8 + (lane & 3) * 2;
        store2(attn + gr * D_MODEL_ + c,       o[nt][0], o[nt][1]);
        store2(attn + (gr + 8) * D_MODEL_ + c, o[nt][2], o[nt][3]);
    }
}

// ---------------- launch -----------------------------------------------------
extern "C" void kernel_launch(void* const* d_in, const int* in_sizes, int n_in,
                              void* d_out, int out_size)
{
    (void)in_sizes; (void)n_in; (void)out_size;
    const float* x  = (const float*)d_in[0];
    const float* wq = (const float*)d_in[1];
    const float* wk = (const float*)d_in[2];
    const float* wv = (const float*)d_in[3];
    const float* wo = (const float*)d_in[4];
    // d_in[5] = mask: causal, known statically — ignored.
    float* out = (float*)d_out;

    __half *xh, *wqkv, *woh, *qkv, *attn;
    cudaGetSymbolAddress((void**)&xh,   g_xh);
    cudaGetSymbolAddress((void**)&wqkv, g_wqkv);
    cudaGetSymbolAddress((void**)&woh,  g_wo);
    cudaGetSymbolAddress((void**)&qkv,  g_qkv);
    cudaGetSymbolAddress((void**)&attn, g_attn);

    // fp32 -> fp16 conversions + rope table
    {
        int n = M_ROWS * D_MODEL_;
        cvt_kernel<<<n / 1024, 256>>>(x, xh, n / 4);
        int m4 = D_MODEL_ * D_MODEL_ / 4;
        cvtw_kernel<<<dim3(m4 / 256, 4), 256>>>(wq, wk, wv, wo, wqkv, woh);
        rope_tab_kernel<<<32, 256>>>();
    }

    // QKV = x @ [Wq;Wk;Wv]^T with fused RoPE on Q,K   (M=8192, N=6144, K=2048)
    cudaFuncSetAttribute(gemm_nt<__half, true>,
                         cudaFuncAttributeMaxDynamicSharedMemorySize, G_SMEM);
    gemm_nt<__half, true><<<dim3(QKV_LD / G_BN, M_ROWS / G_BM), 256, G_SMEM>>>(
        xh, D_MODEL_, wqkv, D_MODEL_, qkv, QKV_LD, D_MODEL_);

    // fused attention, one CTA per (head, batch)
    cudaFuncSetAttribute(attn_kernel, cudaFuncAttributeMaxDynamicSharedMemorySize, ATTN_SMEM);
    attn_kernel<<<dim3(N_HEADS_, B_SZ), 256, ATTN_SMEM>>>(qkv, attn);

    // out = attn @ Wo^T   (M=8192, N=2048, K=2048), fp32 output
    cudaFuncSetAttribute(gemm_nt<float, false>,
                         cudaFuncAttributeMaxDynamicSharedMemorySize, G_SMEM);
    gemm_nt<float, false><<<dim3(D_MODEL_ / G_BN, M_ROWS / G_BM), 256, G_SMEM>>>(
        attn, D_MODEL_, woh, D_MODEL_, out, D_MODEL_, D_MODEL_);
}